// round 12
// baseline (speedup 1.0000x reference)
#include <cuda_runtime.h>
#include <cuda_bf16.h>
#include <cuda_fp16.h>
#include <math.h>
#include <cstdint>

#define EMBED   512
#define HEADS   8
#define HDIM    64
#define TT      6
#define NNODES  30000
#define NGRAPHS 512
#define M_ROWS  (NNODES * TT)   /* 180000 */
#define NCOLS   1024            /* 512 Q cols + 512 K cols */

#define RESID_SCALE    2048.0f          /* 2^11 */
#define RESID_INV      4.8828125e-4f    /* 2^-11 */

/* Scratch */
__device__ float g_qk[(size_t)M_ROWS * NCOLS];
__device__ __half g_Bs[2ull * NCOLS * EMBED];    /* fp16 split planes of [Wq;Wk] */

/* ================= helpers ================= */
__device__ __forceinline__ uint32_t smem_u32(const void* p) {
    uint32_t a;
    asm("{ .reg .u64 t; cvta.to.shared.u64 t, %1; cvt.u32.u64 %0, t; }" : "=r"(a) : "l"(p));
    return a;
}
__device__ __forceinline__ void cp16(uint32_t dst, const void* src, bool pred) {
    int sz = pred ? 16 : 0;
    asm volatile("cp.async.cg.shared.global [%0], [%1], 16, %2;"
                 :: "r"(dst), "l"(src), "r"(sz) : "memory");
}
__device__ __forceinline__ void sts64(uint32_t addr, uint32_t x, uint32_t y) {
    asm volatile("st.shared.v2.u32 [%0], {%1, %2};" :: "r"(addr), "r"(x), "r"(y) : "memory");
}
__device__ __forceinline__ void ldsm_x4(uint32_t* r, uint32_t addr) {
    asm volatile("ldmatrix.sync.aligned.m8n8.x4.shared.b16 {%0,%1,%2,%3}, [%4];"
                 : "=r"(r[0]), "=r"(r[1]), "=r"(r[2]), "=r"(r[3]) : "r"(addr));
}
__device__ __forceinline__ void mma_f16(float* c, const uint32_t* a, const uint32_t* b) {
    asm volatile("mma.sync.aligned.m16n8k16.row.col.f32.f16.f16.f32 "
                 "{%0,%1,%2,%3}, {%4,%5,%6,%7}, {%8,%9}, {%0,%1,%2,%3};"
                 : "+f"(c[0]), "+f"(c[1]), "+f"(c[2]), "+f"(c[3])
                 : "r"(a[0]), "r"(a[1]), "r"(a[2]), "r"(a[3]), "r"(b[0]), "r"(b[1]));
}

/* ========== fp16x2 RN split with scaled residual plane ==========
 * a0 = RN16(x);  a1' = RN16(2^11 * (x - a0))  (normal-range, no subnormals) */
__device__ __forceinline__ void split2s(float x, __half& a0, __half& a1) {
    a0 = __float2half_rn(x);
    a1 = __float2half_rn((x - __half2float(a0)) * RESID_SCALE);
}

/* ================= B-only split kernel (tiny) ================= */
#define B_QUADS ((size_t)NCOLS * EMBED / 4)    /* 131,072 */

__global__ void split_B_kernel(const float* __restrict__ Wq,
                               const float* __restrict__ Wk) {
    size_t p = (size_t)blockIdx.x * blockDim.x + threadIdx.x;
    if (p >= B_QUADS) return;
    size_t i = p * 4;
    size_t j = i >> 9;
    size_t k = i & 511;
    const float* src = (j < 512) ? (Wq + j * 512 + k) : (Wk + (j - 512) * 512 + k);
    float4 x = *(const float4*)src;
    __half a0, a1, b0, b1, c0, c1, d0, d1;
    split2s(x.x, a0, a1);
    split2s(x.y, b0, b1);
    split2s(x.z, c0, c1);
    split2s(x.w, d0, d1);
    __half2 h0 = __half2(a0, b0), h1 = __half2(c0, d0);
    __half2 h2 = __half2(a1, b1), h3 = __half2(c1, d1);
    uint2 p0, p1;
    p0.x = *(uint32_t*)&h0; p0.y = *(uint32_t*)&h1;
    p1.x = *(uint32_t*)&h2; p1.y = *(uint32_t*)&h3;
    const size_t SPQ = (size_t)NCOLS * EMBED / 4;
    ((uint2*)g_Bs)[p] = p0;
    ((uint2*)g_Bs)[SPQ + p] = p1;
}

/* ================= mma.sync fp16x2 GEMM, fused A conversion =========
 * A is read as fp32 X and split in-kernel (bit-identical to split2s
 * pre-pass: same formula, same fp16 planes, same HMMA inputs).
 * c_main: a0*b0.   c_rest: a0*b1' + a1'*b0.
 * result = c_main + (c_rest * 2^-11 + bias).
 * BM=64, BN=64, BK=32. 128 threads, warp tile 32x32, 3-stage, 4 CTAs/SM. */
#define BK          32
#define KCHUNKS     (EMBED / BK)        /* 16 */
#define A_TILE_B    (64 * 64)           /* per split: 64 rows x 64 B */
#define B_TILE_B    (64 * 64)
#define STAGE_B     (2 * A_TILE_B + 2 * B_TILE_B)   /* 16 KB */
#define NSTAGE      3
#define SMEM_TOTAL  (NSTAGE * STAGE_B)              /* 48 KB */

/* B tiles via cp.async (one commit group per chunk) */
__device__ __forceinline__ void load_B(uint32_t sb, int stage, int kc,
                                       int n0, int tid) {
    const size_t SPB = (size_t)NCOLS * EMBED;
    uint32_t base = sb + stage * STAGE_B + 2 * A_TILE_B;
#pragma unroll
    for (int i = 0; i < 4; i++) {
        int o = tid + i * 128;
        int split = o >> 8;
        int rem = o & 255;
        int row = rem >> 2;
        int g = rem & 3;
        int gs = g ^ ((row >> 1) & 3);
        const __half* src = g_Bs + split * SPB
                          + (size_t)(n0 + row) * EMBED + kc * BK + g * 8;
        cp16(base + split * B_TILE_B + row * 64 + gs * 16, src, true);
    }
    asm volatile("cp.async.commit_group;" ::: "memory");
}

/* A: LDG fp32 X into regs (4 x float4 per thread covers 64x32 chunk) */
__device__ __forceinline__ void load_A_regs(float4* st, const float* __restrict__ X,
                                            int m0, int kc, int tid) {
#pragma unroll
    for (int i = 0; i < 4; i++) {
        int o = tid + i * 128;
        int row = o >> 3;
        int f4 = o & 7;
        int m = m0 + row;
        bool v = (m < M_ROWS);
        st[i] = *(const float4*)(X + (size_t)(v ? m : 0) * EMBED + kc * BK + f4 * 4);
    }
}

/* convert regs -> both fp16 planes, STS into swizzled A layout */
__device__ __forceinline__ void store_A_smem(const float4* st, uint32_t slot_base, int tid) {
#pragma unroll
    for (int i = 0; i < 4; i++) {
        int o = tid + i * 128;
        int row = o >> 3;
        int f4 = o & 7;
        int g = f4 >> 1;
        int gs = g ^ ((row >> 1) & 3);
        uint32_t off = row * 64 + gs * 16 + (f4 & 1) * 8;
        __half a0, a1, b0, b1, c0, c1, d0, d1;
        split2s(st[i].x, a0, a1);
        split2s(st[i].y, b0, b1);
        split2s(st[i].z, c0, c1);
        split2s(st[i].w, d0, d1);
        __half2 h0 = __half2(a0, b0), h1 = __half2(c0, d0);
        __half2 h2 = __half2(a1, b1), h3 = __half2(c1, d1);
        sts64(slot_base + off, *(uint32_t*)&h0, *(uint32_t*)&h1);
        sts64(slot_base + A_TILE_B + off, *(uint32_t*)&h2, *(uint32_t*)&h3);
    }
}

__global__ __launch_bounds__(128, 4)
void qk_gemm_mma(const float* __restrict__ X,
                 const float* __restrict__ bq, const float* __restrict__ bk) {
    extern __shared__ char smem[];
    uint32_t sb = smem_u32(smem);
    const int tid = threadIdx.x;
    const int wid = tid >> 5;
    const int lane = tid & 31;
    const int m0 = blockIdx.y * 64;
    const int n0 = blockIdx.x * 64;
    const int warp_m = (wid >> 1) * 32;
    const int warp_n = (wid & 1) * 32;

    float c_main[2][4][4];
    float c_rest[2][4][4];
#pragma unroll
    for (int im = 0; im < 2; im++)
#pragma unroll
        for (int jn = 0; jn < 4; jn++)
#pragma unroll
            for (int q = 0; q < 4; q++) { c_main[im][jn][q] = 0.f; c_rest[im][jn][q] = 0.f; }

    /* prologue: chunks 0,1 — A via LDG+convert+STS, B via cp.async */
    {
        float4 st[4];
        load_A_regs(st, X, m0, 0, tid);
        store_A_smem(st, sb + 0 * STAGE_B, tid);
        load_B(sb, 0, 0, n0, tid);
        load_A_regs(st, X, m0, 1, tid);
        store_A_smem(st, sb + 1 * STAGE_B, tid);
        load_B(sb, 1, 1, n0, tid);
    }

    const int a_r = (lane & 7) + ((lane >> 3) & 1) * 8;
    const int a_g = (lane >> 4) & 1;
    const int b_r = (lane & 7) + ((lane >> 4) & 1) * 8;
    const int b_g = (lane >> 3) & 1;

    for (int kc = 0; kc < KCHUNKS; kc++) {
        const int st_slot = kc % NSTAGE;
        asm volatile("cp.async.wait_group 1;" ::: "memory");
        __syncthreads();   /* B(kc) landed; A STS(kc) visible; slot kc-1 free */

        /* prefetch chunk kc+2: LDG A now (consumed at end), cp.async B now */
        float4 stg[4];
        const bool pf = (kc + NSTAGE - 1 < KCHUNKS);
        if (pf) {
            load_A_regs(stg, X, m0, kc + 2, tid);
            load_B(sb, (kc + 2) % NSTAGE, kc + 2, n0, tid);
        } else {
            asm volatile("cp.async.commit_group;" ::: "memory");
        }

        const uint32_t abase = sb + st_slot * STAGE_B;
        const uint32_t bbase = abase + 2 * A_TILE_B;

#pragma unroll
        for (int ks = 0; ks < 2; ks++) {
            uint32_t bf[2][2][4];
#pragma unroll
            for (int s = 0; s < 2; s++)
#pragma unroll
                for (int j2 = 0; j2 < 2; j2++) {
                    int row = warp_n + j2 * 16 + b_r;
                    int g = ks * 2 + b_g;
                    int gs = g ^ ((row >> 1) & 3);
                    ldsm_x4(bf[s][j2], bbase + s * B_TILE_B + row * 64 + gs * 16);
                }
            {
                uint32_t af[2][4];
#pragma unroll
                for (int im = 0; im < 2; im++) {
                    int row = warp_m + im * 16 + a_r;
                    int g = ks * 2 + a_g;
                    int gs = g ^ ((row >> 1) & 3);
                    ldsm_x4(af[im], abase + 0 * A_TILE_B + row * 64 + gs * 16);
                }
#pragma unroll
                for (int im = 0; im < 2; im++)
#pragma unroll
                    for (int jn = 0; jn < 4; jn++)
                        mma_f16(c_main[im][jn], af[im], &bf[0][jn >> 1][(jn & 1) * 2]);
#pragma unroll
                for (int im = 0; im < 2; im++)
#pragma unroll
                    for (int jn = 0; jn < 4; jn++)
                        mma_f16(c_rest[im][jn], af[im], &bf[1][jn >> 1][(jn & 1) * 2]);
            }
            {
                uint32_t af[2][4];
#pragma unroll
                for (int im = 0; im < 2; im++) {
                    int row = warp_m + im * 16 + a_r;
                    int g = ks * 2 + a_g;
                    int gs = g ^ ((row >> 1) & 3);
                    ldsm_x4(af[im], abase + 1 * A_TILE_B + row * 64 + gs * 16);
                }
#pragma unroll
                for (int im = 0; im < 2; im++)
#pragma unroll
                    for (int jn = 0; jn < 4; jn++)
                        mma_f16(c_rest[im][jn], af[im], &bf[0][jn >> 1][(jn & 1) * 2]);
            }
        }

        /* convert + STS the prefetched A chunk into slot kc+2 */
        if (pf)
            store_A_smem(stg, sb + ((kc + 2) % NSTAGE) * STAGE_B, tid);
    }

    /* epilogue: result = c_main + (c_rest * 2^-11 + bias) */
    const float* bias = (n0 < 512) ? (bq + n0) : (bk + (n0 - 512));
#pragma unroll
    for (int im = 0; im < 2; im++) {
#pragma unroll
        for (int jn = 0; jn < 4; jn++) {
            int col = warp_n + jn * 8 + (lane & 3) * 2;
            float b0 = bias[col], b1 = bias[col + 1];
            int row0 = m0 + warp_m + im * 16 + (lane >> 2);
            if (row0 < M_ROWS) {
                float2 v = make_float2(
                    c_main[im][jn][0] + fmaf(c_rest[im][jn][0], RESID_INV, b0),
                    c_main[im][jn][1] + fmaf(c_rest[im][jn][1], RESID_INV, b1));
                *(float2*)(g_qk + (size_t)row0 * NCOLS + n0 + col) = v;
            }
            int row1 = row0 + 8;
            if (row1 < M_ROWS) {
                float2 v = make_float2(
                    c_main[im][jn][2] + fmaf(c_rest[im][jn][2], RESID_INV, b0),
                    c_main[im][jn][3] + fmaf(c_rest[im][jn][3], RESID_INV, b1));
                *(float2*)(g_qk + (size_t)row1 * NCOLS + n0 + col) = v;
            }
        }
    }
}

/* ================= attention (V in registers, gate inlined) ========== */
#define EPAD (EMBED + 4)

__global__ __launch_bounds__(128)
void attn_kernel(const float* __restrict__ emb,
                 const float* __restrict__ ac,
                 const float* __restrict__ Wg,
                 const float* __restrict__ bg,
                 const int* __restrict__ batch,
                 float* __restrict__ out_ctx,
                 float* __restrict__ out_attn) {
    __shared__ float Qs[TT][EPAD];
    __shared__ float Ks[TT][EPAD];
    __shared__ float Ssc[HEADS][TT][TT];
    __shared__ float Sat[HEADS][TT][TT];
    __shared__ float Sg[TT];

    const int node = blockIdx.x;
    const int tid = threadIdx.x;

    const float4* qkb = (const float4*)(g_qk + (size_t)node * TT * NCOLS);
    const float4* vb  = (const float4*)(emb + (size_t)node * TT * EMBED);

    float4 vreg[TT];
#pragma unroll
    for (int s = 0; s < TT; s++) vreg[s] = vb[s * 128 + tid];

#pragma unroll
    for (int t = 0; t < TT; t++) {
        float4 q = qkb[t * 256 + tid];
        float4 k = qkb[t * 256 + 128 + tid];
        ((float4*)Qs[t])[tid] = q;
        ((float4*)Ks[t])[tid] = k;
    }
    if (tid < TT) {
        int g = batch[node];
        float acc = bg[tid];
#pragma unroll
        for (int j = 0; j < 5; j++) acc += ac[g * 5 + j] * Wg[tid * 5 + j];
        Sg[tid] = acc;
    }
    __syncthreads();

    for (int task = tid; task < HEADS * TT * TT; task += 128) {
        int h = task / 36;
        int r = task % 36;
        int t = r / 6, s = r % 6;
        const float4* qp = (const float4*)&Qs[t][h * HDIM];
        const float4* kp = (const float4*)&Ks[s][h * HDIM];
        float a0 = 0.f;
#pragma unroll
        for (int d = 0; d < 16; d++) {
            float4 a = qp[d], b = kp[d];
            a0 += a.x * b.x + a.y * b.y + a.z * b.z + a.w * b.w;
        }
        Ssc[h][t][s] = a0 * 0.125f * Sg[s];
    }
    __syncthreads();

    if (tid < HEADS * TT) {
        int h = tid / 6, t = tid % 6;
        float sc[6], ab[6];
#pragma unroll
        for (int s = 0; s < 6; s++) {
            sc[s] = Ssc[h][t][s];
            ab[s] = fabsf(sc[s]);
        }
        bool keep[6];
        float mx = -INFINITY;
#pragma unroll
        for (int i = 0; i < 6; i++) {
            int rank = 0;
#pragma unroll
            for (int j = 0; j < 6; j++)
                rank += (ab[j] > ab[i]) || (ab[j] == ab[i] && j < i);
            keep[i] = (rank < 4);
            if (keep[i]) mx = fmaxf(mx, sc[i]);
        }
        float e[6], sum = 0.f;
#pragma unroll
        for (int i = 0; i < 6; i++) {
            e[i] = keep[i] ? expf(sc[i] - mx) : 0.f;
            sum += e[i];
        }
        float inv = 1.0f / sum;
        float* oat = out_attn + (size_t)node * (HEADS * TT * TT) + tid * 6;
#pragma unroll
        for (int i = 0; i < 6; i++) {
            float a = e[i] * inv;
            Sat[h][t][i] = a;
            oat[i] = a;
        }
    }
    __syncthreads();

    float4* octx = (float4*)(out_ctx + (size_t)node * TT * EMBED);
    const int h = tid >> 4;
#pragma unroll
    for (int t = 0; t < TT; t++) {
        float4 a4 = make_float4(0.f, 0.f, 0.f, 0.f);
#pragma unroll
        for (int s = 0; s < 6; s++) {
            float a = Sat[h][t][s];
            float4 v = vreg[s];
            a4.x += a * v.x; a4.y += a * v.y;
            a4.z += a * v.z; a4.w += a * v.w;
        }
        octx[t * 128 + tid] = a4;
    }
}

/* ================= launch ================= */
extern "C" void kernel_launch(void* const* d_in, const int* in_sizes, int n_in,
                              void* d_out, int out_size) {
    const float* emb   = (const float*)d_in[0];
    const float* ac    = (const float*)d_in[1];
    const float* Wk    = (const float*)d_in[2];
    const float* bk    = (const float*)d_in[3];
    const float* Wq    = (const float*)d_in[4];
    const float* bq    = (const float*)d_in[5];
    const float* Wg    = (const float*)d_in[6];
    const float* bg    = (const float*)d_in[7];
    const int*   batch = (const int*)d_in[8];

    float* out = (float*)d_out;
    float* out_ctx  = out;
    float* out_attn = out + (size_t)NNODES * TT * EMBED;

    split_B_kernel<<<(unsigned)((B_QUADS + 255) / 256), 256>>>(Wq, Wk);

    cudaFuncSetAttribute(qk_gemm_mma, cudaFuncAttributeMaxDynamicSharedMemorySize, SMEM_TOTAL);
    qk_gemm_mma<<<dim3(NCOLS / 64, (M_ROWS + 63) / 64), 128, SMEM_TOTAL>>>(emb, bq, bk);

    attn_kernel<<<NNODES, 128>>>(emb, ac, Wg, bg, batch, out_ctx, out_attn);
}

// round 15
// speedup vs baseline: 1.6136x; 1.6136x over previous
#include <cuda_runtime.h>
#include <cuda_bf16.h>
#include <cuda_fp16.h>
#include <math.h>
#include <cstdint>

#define EMBED   512
#define HEADS   8
#define HDIM    64
#define TT      6
#define NNODES  30000
#define NGRAPHS 512
#define M_ROWS  (NNODES * TT)   /* 180000 */
#define NCOLS   1024            /* 512 Q cols + 512 K cols */

#define RESID_SCALE    2048.0f          /* 2^11 */
#define RESID_INV      4.8828125e-4f    /* 2^-11 */

/* Scratch */
__device__ float g_qk[(size_t)M_ROWS * NCOLS];
__device__ __half g_As[2ull * M_ROWS * EMBED];   /* fp16 split planes of X  */
__device__ __half g_Bs[2ull * NCOLS * EMBED];    /* fp16 split planes of [Wq;Wk] */

/* ================= helpers ================= */
__device__ __forceinline__ uint32_t smem_u32(const void* p) {
    uint32_t a;
    asm("{ .reg .u64 t; cvta.to.shared.u64 t, %1; cvt.u32.u64 %0, t; }" : "=r"(a) : "l"(p));
    return a;
}
__device__ __forceinline__ void cp16(uint32_t dst, const void* src, bool pred) {
    int sz = pred ? 16 : 0;
    asm volatile("cp.async.cg.shared.global [%0], [%1], 16, %2;"
                 :: "r"(dst), "l"(src), "r"(sz) : "memory");
}
__device__ __forceinline__ void ldsm_x4(uint32_t* r, uint32_t addr) {
    asm volatile("ldmatrix.sync.aligned.m8n8.x4.shared.b16 {%0,%1,%2,%3}, [%4];"
                 : "=r"(r[0]), "=r"(r[1]), "=r"(r[2]), "=r"(r[3]) : "r"(addr));
}
__device__ __forceinline__ void mma_f16(float* c, const uint32_t* a, const uint32_t* b) {
    asm volatile("mma.sync.aligned.m16n8k16.row.col.f32.f16.f16.f32 "
                 "{%0,%1,%2,%3}, {%4,%5,%6,%7}, {%8,%9}, {%0,%1,%2,%3};"
                 : "+f"(c[0]), "+f"(c[1]), "+f"(c[2]), "+f"(c[3])
                 : "r"(a[0]), "r"(a[1]), "r"(a[2]), "r"(a[3]), "r"(b[0]), "r"(b[1]));
}
__device__ __forceinline__ void stg_cs_f2(float* p, float x, float y) {
    asm volatile("st.global.cs.v2.f32 [%0], {%1, %2};" :: "l"(p), "f"(x), "f"(y) : "memory");
}
__device__ __forceinline__ void stg_cs_u2(void* p, uint2 v) {
    asm volatile("st.global.cs.v2.u32 [%0], {%1, %2};" :: "l"(p), "r"(v.x), "r"(v.y) : "memory");
}
__device__ __forceinline__ float4 ldg_cs_f4(const float4* p) {
    float4 v;
    asm volatile("ld.global.cs.v4.f32 {%0,%1,%2,%3}, [%4];"
                 : "=f"(v.x), "=f"(v.y), "=f"(v.z), "=f"(v.w) : "l"(p));
    return v;
}

/* ========== fp16x2 RN split with scaled residual plane ==========
 * a0 = RN16(x);  a1' = RN16(2^11 * (x - a0))  (normal-range, no subnormals) */
__device__ __forceinline__ void split2s(float x, __half& a0, __half& a1) {
    a0 = __float2half_rn(x);
    a1 = __float2half_rn((x - __half2float(a0)) * RESID_SCALE);
}

/* ================= merged split kernel (A then B), float4-wide ========= */
#define A_QUADS ((size_t)M_ROWS * EMBED / 4)   /* 23,040,000 */
#define B_QUADS ((size_t)NCOLS * EMBED / 4)    /* 131,072 */

__device__ __forceinline__ void split_quad(float4 x, uint2& p0, uint2& p1) {
    __half a0, a1, b0, b1, c0, c1, d0, d1;
    split2s(x.x, a0, a1);
    split2s(x.y, b0, b1);
    split2s(x.z, c0, c1);
    split2s(x.w, d0, d1);
    __half2 h0 = __half2(a0, b0), h1 = __half2(c0, d0);
    __half2 h2 = __half2(a1, b1), h3 = __half2(c1, d1);
    p0.x = *(uint32_t*)&h0; p0.y = *(uint32_t*)&h1;
    p1.x = *(uint32_t*)&h2; p1.y = *(uint32_t*)&h3;
}

__global__ void split_kernel(const float* __restrict__ X,
                             const float* __restrict__ Wq,
                             const float* __restrict__ Wk) {
    size_t gid = (size_t)blockIdx.x * blockDim.x + threadIdx.x;
    if (gid < A_QUADS) {
        float4 x = ldg_cs_f4((const float4*)X + gid);
        uint2 p0, p1;
        split_quad(x, p0, p1);
        const size_t SPQ = (size_t)M_ROWS * EMBED / 4;   /* quads per plane */
        stg_cs_u2((uint2*)g_As + gid, p0);
        stg_cs_u2((uint2*)g_As + SPQ + gid, p1);
    } else if (gid < A_QUADS + B_QUADS) {
        size_t p = gid - A_QUADS;
        size_t i = p * 4;
        size_t j = i >> 9;
        size_t k = i & 511;
        const float* src = (j < 512) ? (Wq + j * 512 + k) : (Wk + (j - 512) * 512 + k);
        float4 x = *(const float4*)src;
        uint2 p0, p1;
        split_quad(x, p0, p1);
        const size_t SPQ = (size_t)NCOLS * EMBED / 4;
        ((uint2*)g_Bs)[p] = p0;
        ((uint2*)g_Bs)[SPQ + p] = p1;
    }
}

/* ================= mma.sync fp16x2 GEMM, 3 products, dual-class =====
 * c_main: a0*b0.   c_rest: a0*b1' + a1'*b0   (both carry 2^11 factor).
 * result = c_main + (c_rest * 2^-11 + bias).
 * BM=64, BN=64, BK=32. 128 threads (4 warps, 2x2 warp grid, tile 32x32).
 * 3-stage cp.async pipeline, 4 CTAs/SM.  (R10 structure - best known)   */
#define BK          32
#define KCHUNKS     (EMBED / BK)        /* 16 */
#define A_TILE_B    (64 * 64)           /* per split: 64 rows x 64 B */
#define B_TILE_B    (64 * 64)
#define STAGE_B     (2 * A_TILE_B + 2 * B_TILE_B)   /* 16 KB */
#define NSTAGE      3
#define SMEM_TOTAL  (NSTAGE * STAGE_B)              /* 48 KB */

__device__ __forceinline__ void load_chunk(uint32_t sb, int stage, int kc,
                                           int m0, int n0, int tid) {
    const size_t SPA = (size_t)M_ROWS * EMBED;
    const size_t SPB = (size_t)NCOLS * EMBED;
    uint32_t base = sb + stage * STAGE_B;
#pragma unroll
    for (int i = 0; i < 4; i++) {
        int o = tid + i * 128;
        int split = o >> 8;
        int rem = o & 255;
        int row = rem >> 2;
        int g = rem & 3;
        int gs = g ^ ((row >> 1) & 3);
        int m = m0 + row;
        bool v = (m < M_ROWS);
        const __half* src = g_As + split * SPA
                          + (size_t)(v ? m : 0) * EMBED + kc * BK + g * 8;
        cp16(base + split * A_TILE_B + row * 64 + gs * 16, src, v);
    }
#pragma unroll
    for (int i = 0; i < 4; i++) {
        int o = tid + i * 128;
        int split = o >> 8;
        int rem = o & 255;
        int row = rem >> 2;
        int g = rem & 3;
        int gs = g ^ ((row >> 1) & 3);
        const __half* src = g_Bs + split * SPB
                          + (size_t)(n0 + row) * EMBED + kc * BK + g * 8;
        cp16(base + 2 * A_TILE_B + split * B_TILE_B + row * 64 + gs * 16, src, true);
    }
    asm volatile("cp.async.commit_group;" ::: "memory");
}

__global__ __launch_bounds__(128, 4)
void qk_gemm_mma(const float* __restrict__ bq, const float* __restrict__ bk) {
    extern __shared__ char smem[];
    uint32_t sb = smem_u32(smem);
    const int tid = threadIdx.x;
    const int wid = tid >> 5;
    const int lane = tid & 31;
    const int m0 = blockIdx.y * 64;
    const int n0 = blockIdx.x * 64;
    const int warp_m = (wid >> 1) * 32;
    const int warp_n = (wid & 1) * 32;

    float c_main[2][4][4];
    float c_rest[2][4][4];
#pragma unroll
    for (int im = 0; im < 2; im++)
#pragma unroll
        for (int jn = 0; jn < 4; jn++)
#pragma unroll
            for (int q = 0; q < 4; q++) { c_main[im][jn][q] = 0.f; c_rest[im][jn][q] = 0.f; }

    load_chunk(sb, 0, 0, m0, n0, tid);
    load_chunk(sb, 1, 1, m0, n0, tid);

    const int a_r = (lane & 7) + ((lane >> 3) & 1) * 8;
    const int a_g = (lane >> 4) & 1;
    const int b_r = (lane & 7) + ((lane >> 4) & 1) * 8;
    const int b_g = (lane >> 3) & 1;

    for (int kc = 0; kc < KCHUNKS; kc++) {
        const int st = kc % NSTAGE;
        asm volatile("cp.async.wait_group 1;" ::: "memory");
        __syncthreads();

        if (kc + NSTAGE - 1 < KCHUNKS)
            load_chunk(sb, (kc + NSTAGE - 1) % NSTAGE, kc + NSTAGE - 1, m0, n0, tid);
        else
            asm volatile("cp.async.commit_group;" ::: "memory");

        const uint32_t abase = sb + st * STAGE_B;
        const uint32_t bbase = abase + 2 * A_TILE_B;

#pragma unroll
        for (int ks = 0; ks < 2; ks++) {
            uint32_t bf[2][2][4];
#pragma unroll
            for (int s = 0; s < 2; s++)
#pragma unroll
                for (int j2 = 0; j2 < 2; j2++) {
                    int row = warp_n + j2 * 16 + b_r;
                    int g = ks * 2 + b_g;
                    int gs = g ^ ((row >> 1) & 3);
                    ldsm_x4(bf[s][j2], bbase + s * B_TILE_B + row * 64 + gs * 16);
                }
            {
                uint32_t af[2][4];
#pragma unroll
                for (int im = 0; im < 2; im++) {
                    int row = warp_m + im * 16 + a_r;
                    int g = ks * 2 + a_g;
                    int gs = g ^ ((row >> 1) & 3);
                    ldsm_x4(af[im], abase + 0 * A_TILE_B + row * 64 + gs * 16);
                }
#pragma unroll
                for (int im = 0; im < 2; im++)
#pragma unroll
                    for (int jn = 0; jn < 4; jn++)
                        mma_f16(c_main[im][jn], af[im], &bf[0][jn >> 1][(jn & 1) * 2]);
#pragma unroll
                for (int im = 0; im < 2; im++)
#pragma unroll
                    for (int jn = 0; jn < 4; jn++)
                        mma_f16(c_rest[im][jn], af[im], &bf[1][jn >> 1][(jn & 1) * 2]);
            }
            {
                uint32_t af[2][4];
#pragma unroll
                for (int im = 0; im < 2; im++) {
                    int row = warp_m + im * 16 + a_r;
                    int g = ks * 2 + a_g;
                    int gs = g ^ ((row >> 1) & 3);
                    ldsm_x4(af[im], abase + 1 * A_TILE_B + row * 64 + gs * 16);
                }
#pragma unroll
                for (int im = 0; im < 2; im++)
#pragma unroll
                    for (int jn = 0; jn < 4; jn++)
                        mma_f16(c_rest[im][jn], af[im], &bf[0][jn >> 1][(jn & 1) * 2]);
            }
        }
    }

    /* epilogue: result = c_main + (c_rest * 2^-11 + bias); streaming stores */
    const float* bias = (n0 < 512) ? (bq + n0) : (bk + (n0 - 512));
#pragma unroll
    for (int im = 0; im < 2; im++) {
#pragma unroll
        for (int jn = 0; jn < 4; jn++) {
            int col = warp_n + jn * 8 + (lane & 3) * 2;
            float b0 = bias[col], b1 = bias[col + 1];
            int row0 = m0 + warp_m + im * 16 + (lane >> 2);
            if (row0 < M_ROWS) {
                stg_cs_f2(g_qk + (size_t)row0 * NCOLS + n0 + col,
                          c_main[im][jn][0] + fmaf(c_rest[im][jn][0], RESID_INV, b0),
                          c_main[im][jn][1] + fmaf(c_rest[im][jn][1], RESID_INV, b1));
            }
            int row1 = row0 + 8;
            if (row1 < M_ROWS) {
                stg_cs_f2(g_qk + (size_t)row1 * NCOLS + n0 + col,
                          c_main[im][jn][2] + fmaf(c_rest[im][jn][2], RESID_INV, b0),
                          c_main[im][jn][3] + fmaf(c_rest[im][jn][3], RESID_INV, b1));
            }
        }
    }
}

/* ================= attention (V in registers, gate inlined) ========== */
#define EPAD (EMBED + 4)

__global__ __launch_bounds__(128)
void attn_kernel(const float* __restrict__ emb,
                 const float* __restrict__ ac,
                 const float* __restrict__ Wg,
                 const float* __restrict__ bg,
                 const int* __restrict__ batch,
                 float* __restrict__ out_ctx,
                 float* __restrict__ out_attn) {
    __shared__ float Qs[TT][EPAD];
    __shared__ float Ks[TT][EPAD];
    __shared__ float Ssc[HEADS][TT][TT];
    __shared__ float Sat[HEADS][TT][TT];
    __shared__ float Sg[TT];

    const int node = blockIdx.x;
    const int tid = threadIdx.x;

    const float4* qkb = (const float4*)(g_qk + (size_t)node * TT * NCOLS);
    const float4* vb  = (const float4*)(emb + (size_t)node * TT * EMBED);

    float4 vreg[TT];
#pragma unroll
    for (int s = 0; s < TT; s++) vreg[s] = vb[s * 128 + tid];

    /* Q/K rows into smem (streaming loads — single use of g_qk) */
#pragma unroll
    for (int t = 0; t < TT; t++) {
        float4 q = ldg_cs_f4(qkb + t * 256 + tid);
        float4 k = ldg_cs_f4(qkb + t * 256 + 128 + tid);
        ((float4*)Qs[t])[tid] = q;
        ((float4*)Ks[t])[tid] = k;
    }
    if (tid < TT) {
        int g = batch[node];
        float acc = bg[tid];
#pragma unroll
        for (int j = 0; j < 5; j++) acc += ac[g * 5 + j] * Wg[tid * 5 + j];
        Sg[tid] = acc;
    }
    __syncthreads();

    for (int task = tid; task < HEADS * TT * TT; task += 128) {
        int h = task / 36;
        int r = task % 36;
        int t = r / 6, s = r % 6;
        const float4* qp = (const float4*)&Qs[t][h * HDIM];
        const float4* kp = (const float4*)&Ks[s][h * HDIM];
        float a0 = 0.f;
#pragma unroll
        for (int d = 0; d < 16; d++) {
            float4 a = qp[d], b = kp[d];
            a0 += a.x * b.x + a.y * b.y + a.z * b.z + a.w * b.w;
        }
        Ssc[h][t][s] = a0 * 0.125f * Sg[s];
    }
    __syncthreads();

    if (tid < HEADS * TT) {
        int h = tid / 6, t = tid % 6;
        float sc[6], ab[6];
#pragma unroll
        for (int s = 0; s < 6; s++) {
            sc[s] = Ssc[h][t][s];
            ab[s] = fabsf(sc[s]);
        }
        bool keep[6];
        float mx = -INFINITY;
#pragma unroll
        for (int i = 0; i < 6; i++) {
            int rank = 0;
#pragma unroll
            for (int j = 0; j < 6; j++)
                rank += (ab[j] > ab[i]) || (ab[j] == ab[i] && j < i);
            keep[i] = (rank < 4);
            if (keep[i]) mx = fmaxf(mx, sc[i]);
        }
        float e[6], sum = 0.f;
#pragma unroll
        for (int i = 0; i < 6; i++) {
            e[i] = keep[i] ? expf(sc[i] - mx) : 0.f;
            sum += e[i];
        }
        float inv = 1.0f / sum;
        float* oat = out_attn + (size_t)node * (HEADS * TT * TT) + tid * 6;
#pragma unroll
        for (int i = 0; i < 6; i++) {
            float a = e[i] * inv;
            Sat[h][t][i] = a;
            oat[i] = a;
        }
    }
    __syncthreads();

    float4* octx = (float4*)(out_ctx + (size_t)node * TT * EMBED);
    const int h = tid >> 4;
#pragma unroll
    for (int t = 0; t < TT; t++) {
        float4 a4 = make_float4(0.f, 0.f, 0.f, 0.f);
#pragma unroll
        for (int s = 0; s < 6; s++) {
            float a = Sat[h][t][s];
            float4 v = vreg[s];
            a4.x += a * v.x; a4.y += a * v.y;
            a4.z += a * v.z; a4.w += a * v.w;
        }
        octx[t * 128 + tid] = a4;
    }
}

/* ================= launch ================= */
extern "C" void kernel_launch(void* const* d_in, const int* in_sizes, int n_in,
                              void* d_out, int out_size) {
    const float* emb   = (const float*)d_in[0];
    const float* ac    = (const float*)d_in[1];
    const float* Wk    = (const float*)d_in[2];
    const float* bk    = (const float*)d_in[3];
    const float* Wq    = (const float*)d_in[4];
    const float* bq    = (const float*)d_in[5];
    const float* Wg    = (const float*)d_in[6];
    const float* bg    = (const float*)d_in[7];
    const int*   batch = (const int*)d_in[8];

    float* out = (float*)d_out;
    float* out_ctx  = out;
    float* out_attn = out + (size_t)NNODES * TT * EMBED;

    size_t tot_quads = A_QUADS + B_QUADS;
    split_kernel<<<(unsigned)((tot_quads + 255) / 256), 256>>>(emb, Wq, Wk);

    cudaFuncSetAttribute(qk_gemm_mma, cudaFuncAttributeMaxDynamicSharedMemorySize, SMEM_TOTAL);
    qk_gemm_mma<<<dim3(NCOLS / 64, (M_ROWS + 63) / 64), 128, SMEM_TOTAL>>>(bq, bk);

    attn_kernel<<<NNODES, 128>>>(emb, ac, Wg, bg, batch, out_ctx, out_attn);
}